// round 4
// baseline (speedup 1.0000x reference)
#include <cuda_runtime.h>
#include <cuda_bf16.h>

// PyramidROIAlign R4: one block per box; one WARP per pool cell, 8 channels
// per thread (2x float4) -> 8 independent LDG.128 in flight per thread.
// Phase 1 (threads 0..48) precomputes per-cell corner byte-offsets + weights.

#define POOL_W 7
#define NCELLS 49
#define NCH    256
#define NBOXES 1000
#define NBATCH 2

struct CellParam {
    int   o00, o01, o10, o11;   // byte offsets of the 4 corner pixels (channel 0)
    float wx, wy, vm, pad;
};

__global__ __launch_bounds__(256) void pyramid_roi_align_kernel(
    const float* __restrict__ boxes,
    const float* __restrict__ p3,      // [B,128,128,C]
    const float* __restrict__ p4,      // [B,64,64,C]
    const float* __restrict__ p5,      // [B,32,32,C]
    float* __restrict__ out)           // [B*N, 7, 7, C]
{
    __shared__ CellParam cp[NCELLS];

    const int box  = blockIdx.x;
    const int tid  = threadIdx.x;
    const int warp = tid >> 5;         // 0..7 : cell group
    const int lane = tid & 31;         // float4 channel group (first half)
    const int b    = (box >= NBOXES) ? 1 : 0;

    // ---- box scalars (broadcast loads; all threads) ----
    const float y1 = __ldg(boxes + box * 4 + 0);
    const float x1 = __ldg(boxes + box * 4 + 1);
    const float y2 = __ldg(boxes + box * 4 + 2);
    const float x2 = __ldg(boxes + box * 4 + 3);
    const float h  = y2 - y1;
    const float w  = x2 - x1;

    float lvlf = ceilf(5.0f + logf(h * w) / 0.6931471805599453f);
    lvlf = fminf(fmaxf(lvlf, 3.0f), 5.0f);
    const int level = (int)lvlf;

    const float* feat;
    int HW;
    if (level == 3)      { feat = p3; HW = 128; }
    else if (level == 4) { feat = p4; HW = 64;  }
    else                 { feat = p5; HW = 32;  }

    // ---- phase 1: per-cell params (threads 0..48), exact reference rounding ----
    if (tid < NCELLS) {
        const float Hm1 = (float)(HW - 1);
        const int   iy  = tid / POOL_W;
        const int   ix  = tid - iy * POOL_W;
        const float stepy = __fdiv_rn(__fmul_rn(h, Hm1), 6.0f);
        const float stepx = __fdiv_rn(__fmul_rn(w, Hm1), 6.0f);
        const float ys = __fadd_rn(__fmul_rn(y1, Hm1), __fmul_rn((float)iy, stepy));
        const float xs = __fadd_rn(__fmul_rn(x1, Hm1), __fmul_rn((float)ix, stepx));

        const bool valid = (ys >= 0.0f) & (ys <= Hm1) & (xs >= 0.0f) & (xs <= Hm1);

        const float y0f = floorf(ys);
        const float x0f = floorf(xs);

        const int y0i = (int)fminf(fmaxf(y0f, 0.0f), Hm1);
        const int y1i = (int)fminf(fmaxf(y0f + 1.0f, 0.0f), Hm1);
        const int x0i = (int)fminf(fmaxf(x0f, 0.0f), Hm1);
        const int x1i = (int)fminf(fmaxf(x0f + 1.0f, 0.0f), Hm1);

        const int rowbytes = HW * NCH * 4;
        cp[tid].o00 = y0i * rowbytes + x0i * (NCH * 4);
        cp[tid].o01 = y0i * rowbytes + x1i * (NCH * 4);
        cp[tid].o10 = y1i * rowbytes + x0i * (NCH * 4);
        cp[tid].o11 = y1i * rowbytes + x1i * (NCH * 4);
        cp[tid].wx  = xs - x0f;
        cp[tid].wy  = ys - y0f;
        cp[tid].vm  = valid ? 1.0f : 0.0f;
    }
    __syncthreads();

    // ---- phase 2: one warp per cell, 8 channels (2x float4) per thread ----
    const char* bp0 = (const char*)(feat + (size_t)b * HW * HW * NCH) + lane * 16;
    const char* bp1 = bp0 + 512;                       // second half of channels
    float4* outp0 = (float4*)out + (size_t)box * NCELLS * (NCH / 4) + lane;
    float4* outp1 = outp0 + 32;

    #pragma unroll 1
    for (int c = warp; c < NCELLS; c += 8) {
        const int   o00 = cp[c].o00;
        const int   o01 = cp[c].o01;
        const int   o10 = cp[c].o10;
        const int   o11 = cp[c].o11;
        const float wx  = cp[c].wx;
        const float wy  = cp[c].wy;
        const float vm  = cp[c].vm;

        // 8 independent 128-bit loads
        const float4 a00 = __ldg((const float4*)(bp0 + o00));
        const float4 a01 = __ldg((const float4*)(bp0 + o01));
        const float4 a10 = __ldg((const float4*)(bp0 + o10));
        const float4 a11 = __ldg((const float4*)(bp0 + o11));
        const float4 b00 = __ldg((const float4*)(bp1 + o00));
        const float4 b01 = __ldg((const float4*)(bp1 + o01));
        const float4 b10 = __ldg((const float4*)(bp1 + o10));
        const float4 b11 = __ldg((const float4*)(bp1 + o11));

        const float owx = 1.0f - wx;
        const float owy = 1.0f - wy;

        float4 oa, ob;
        oa.x = ((a00.x * owx + a01.x * wx) * owy + (a10.x * owx + a11.x * wx) * wy) * vm;
        oa.y = ((a00.y * owx + a01.y * wx) * owy + (a10.y * owx + a11.y * wx) * wy) * vm;
        oa.z = ((a00.z * owx + a01.z * wx) * owy + (a10.z * owx + a11.z * wx) * wy) * vm;
        oa.w = ((a00.w * owx + a01.w * wx) * owy + (a10.w * owx + a11.w * wx) * wy) * vm;
        ob.x = ((b00.x * owx + b01.x * wx) * owy + (b10.x * owx + b11.x * wx) * wy) * vm;
        ob.y = ((b00.y * owx + b01.y * wx) * owy + (b10.y * owx + b11.y * wx) * wy) * vm;
        ob.z = ((b00.z * owx + b01.z * wx) * owy + (b10.z * owx + b11.z * wx) * wy) * vm;
        ob.w = ((b00.w * owx + b01.w * wx) * owy + (b10.w * owx + b11.w * wx) * wy) * vm;

        __stcs(outp0 + (size_t)c * (NCH / 4), oa);
        __stcs(outp1 + (size_t)c * (NCH / 4), ob);
    }
}

extern "C" void kernel_launch(void* const* d_in, const int* in_sizes, int n_in,
                              void* d_out, int out_size) {
    const float* boxes = (const float*)d_in[0];
    const float* p3    = (const float*)d_in[2];
    const float* p4    = (const float*)d_in[3];
    const float* p5    = (const float*)d_in[4];
    float* out = (float*)d_out;

    pyramid_roi_align_kernel<<<NBATCH * NBOXES, 256>>>(boxes, p3, p4, p5, out);
}